// round 15
// baseline (speedup 1.0000x reference)
#include <cuda_runtime.h>
#include <cuda_bf16.h>
#include <cuda_fp16.h>
#include <math.h>

// Problem constants
#define PP   256
#define FF   20
#define HH   18
#define WW   18
#define HW   (HH*WW)      // 324
#define VOL  (FF*HH*WW)   // 6480
#define MAXB 4096
#define PI_F 3.14159f

// Sampler pair volume: per layer 21 rows x 21 half2, 20 layers
#define PROW 21
#define PLAY (PROW*PROW)  // 441
#define PVOL (FF*PLAY)    // 8820 half2 = 35280 B

// Device scratch: hidden activations
__device__ float g_h[MAXB * PP];

// ---------------------------------------------------------------------------
// f32x2 helpers (FFMA2 via PTX)
// ---------------------------------------------------------------------------
typedef unsigned long long u64;

__device__ __forceinline__ u64 pack2(float lo, float hi) {
    u64 d;
    asm("mov.b64 %0, {%1, %2};" : "=l"(d)
        : "r"(__float_as_uint(lo)), "r"(__float_as_uint(hi)));
    return d;
}
__device__ __forceinline__ u64 pack2dup(float v) {
    u64 d;
    asm("mov.b64 %0, {%1, %1};" : "=l"(d) : "r"(__float_as_uint(v)));
    return d;
}
__device__ __forceinline__ u64 fma2(u64 a, u64 b, u64 c) {
    u64 d;
    asm("fma.rn.f32x2 %0, %1, %2, %3;" : "=l"(d) : "l"(a), "l"(b), "l"(c));
    return d;
}
__device__ __forceinline__ float2 unpack2(u64 v) {
    unsigned lo, hi;
    asm("mov.b64 {%0, %1}, %2;" : "=r"(lo), "=r"(hi) : "l"(v));
    float2 f; f.x = __uint_as_float(lo); f.y = __uint_as_float(hi);
    return f;
}

// ---------------------------------------------------------------------------
// Kernel 1: h = relu(pc @ W1 + b1), double-buffered tiled SGEMM (R13-proven).
// BM=64, BN=64, BK=32, 256 threads, 4x4 thread tile, grid (B/64, 4).
// ---------------------------------------------------------------------------
#define K1_BM 64
#define K1_BN 64
#define K1_BK 32
#define K1_AS 68
#define NKT   (PP / K1_BK)   // 8

__global__ __launch_bounds__(256) void adaat_hidden_kernel(
    const float* __restrict__ pc, int B,
    const float* __restrict__ W1, const float* __restrict__ b1)
{
    __shared__ float As[2][K1_BK * K1_AS];
    __shared__ float Bs[2][K1_BK * K1_AS];

    const int b0  = blockIdx.x * K1_BM;
    const int n0  = blockIdx.y * K1_BN;
    const int tid = threadIdx.x;
    const int tc  = tid & 15;
    const int tr  = tid >> 4;

    float ra[8], rb[8];

    #pragma unroll
    for (int p = 0; p < 8; p++) {
        int idx = p * 256 + tid;
        int row = idx >> 5, kk = idx & 31;
        ra[p] = (b0 + row < B) ? pc[(size_t)(b0 + row) * PP + kk] : 0.f;
    }
    #pragma unroll
    for (int p = 0; p < 8; p++) {
        int idx = p * 256 + tid;
        int kk = idx >> 6, col = idx & 63;
        rb[p] = W1[(size_t)kk * PP + n0 + col];
    }
    #pragma unroll
    for (int p = 0; p < 8; p++) {
        int idx = p * 256 + tid;
        int row = idx >> 5, kk = idx & 31;
        As[0][kk * K1_AS + row] = ra[p];
    }
    #pragma unroll
    for (int p = 0; p < 8; p++) {
        int idx = p * 256 + tid;
        int kk = idx >> 6, col = idx & 63;
        Bs[0][kk * K1_AS + col] = rb[p];
    }
    __syncthreads();

    u64 acc[4][2];
    {
        float4 bj = *(const float4*)(b1 + n0 + tc * 4);
        u64 lo = pack2(bj.x, bj.y), hi = pack2(bj.z, bj.w);
        #pragma unroll
        for (int i = 0; i < 4; i++) { acc[i][0] = lo; acc[i][1] = hi; }
    }

    for (int it = 0; it < NKT; it++) {
        const int cur = it & 1;
        const int nxt = cur ^ 1;

        if (it < NKT - 1) {
            int kt = (it + 1) * K1_BK;
            #pragma unroll
            for (int p = 0; p < 8; p++) {
                int idx = p * 256 + tid;
                int row = idx >> 5, kk = idx & 31;
                ra[p] = (b0 + row < B) ? pc[(size_t)(b0 + row) * PP + kt + kk] : 0.f;
            }
            #pragma unroll
            for (int p = 0; p < 8; p++) {
                int idx = p * 256 + tid;
                int kk = idx >> 6, col = idx & 63;
                rb[p] = W1[(size_t)(kt + kk) * PP + n0 + col];
            }
        }

        #pragma unroll
        for (int kk = 0; kk < K1_BK; kk++) {
            float4 a = *(const float4*)(&As[cur][kk * K1_AS + tr * 4]);
            float4 w = *(const float4*)(&Bs[cur][kk * K1_AS + tc * 4]);
            u64 wlo = pack2(w.x, w.y), whi = pack2(w.z, w.w);
            u64 a0 = pack2dup(a.x), a1 = pack2dup(a.y);
            u64 a2 = pack2dup(a.z), a3 = pack2dup(a.w);
            acc[0][0] = fma2(a0, wlo, acc[0][0]); acc[0][1] = fma2(a0, whi, acc[0][1]);
            acc[1][0] = fma2(a1, wlo, acc[1][0]); acc[1][1] = fma2(a1, whi, acc[1][1]);
            acc[2][0] = fma2(a2, wlo, acc[2][0]); acc[2][1] = fma2(a2, whi, acc[2][1]);
            acc[3][0] = fma2(a3, wlo, acc[3][0]); acc[3][1] = fma2(a3, whi, acc[3][1]);
        }

        if (it < NKT - 1) {
            #pragma unroll
            for (int p = 0; p < 8; p++) {
                int idx = p * 256 + tid;
                int row = idx >> 5, kk = idx & 31;
                As[nxt][kk * K1_AS + row] = ra[p];
            }
            #pragma unroll
            for (int p = 0; p < 8; p++) {
                int idx = p * 256 + tid;
                int kk = idx >> 6, col = idx & 63;
                Bs[nxt][kk * K1_AS + col] = rb[p];
            }
        }
        __syncthreads();
    }

    #pragma unroll
    for (int i = 0; i < 4; i++) {
        int row = b0 + tr * 4 + i;
        if (row >= B) break;
        float2 v0 = unpack2(acc[i][0]);
        float2 v1 = unpack2(acc[i][1]);
        float4 o;
        o.x = fmaxf(v0.x, 0.f); o.y = fmaxf(v0.y, 0.f);
        o.z = fmaxf(v1.x, 0.f); o.w = fmaxf(v1.y, 0.f);
        *(float4*)(g_h + (size_t)row * PP + n0 + tc * 4) = o;
    }
}

// ---------------------------------------------------------------------------
// Kernel 2: trilinear sample with INLINE head GEMV.
// One CTA per batch, block (18,18). During the fill phase, threads 0..319
// each compute a 64-MAC partial of one head column (h row is L2-hot from
// kernel 1; W columns are L2-resident). Setup threads then reduce + activate.
// Sampler body is the R11-proven code.
// ---------------------------------------------------------------------------
__global__ __launch_bounds__(324) void adaat_sample_kernel(
    const float* __restrict__ fm, float* __restrict__ out,
    const float* __restrict__ bs, const float* __restrict__ br,
    const float* __restrict__ bt,
    const float* __restrict__ Ws, const float* __restrict__ Wr,
    const float* __restrict__ Wt)
{
    const int b   = blockIdx.x;
    const int tx  = threadIdx.x;      // 0..17
    const int ty  = threadIdx.y;      // 0..17
    const int tid = ty * WW + tx;

    __shared__ __half2 pairs[PVOL];   // 35280 B
    __shared__ float4  cfA[FF];       // axx, axy, cx, zw0
    __shared__ float4  cfB[FF];       // ayx, ayy, cy, zw1
    __shared__ int2    zb[FF];
    __shared__ float   hpart[320];    // head partials [col*4 + quarter]

    // phase 0: zero pair volume
    {
        float4* p4 = (float4*)pairs;
        for (int i = tid; i < PVOL / 4; i += HW)
            p4[i] = make_float4(0.f, 0.f, 0.f, 0.f);
    }
    __syncthreads();

    // phase 1a: head GEMV partials (threads 0..319)
    if (tid < 320) {
        const int c  = tid >> 2;      // head col 0..79
        const int qq = tid & 3;       // k quarter
        const float* hrow = g_h + (size_t)b * PP + qq * 64;
        const float* wcol; int ld;
        if (c < 20)      { wcol = Ws + c;        ld = 20; }
        else if (c < 40) { wcol = Wr + (c - 20); ld = 20; }
        else             { wcol = Wt + (c - 40); ld = 40; }
        wcol += (size_t)(qq * 64) * ld;

        float acc = 0.f;
        #pragma unroll 4
        for (int k4 = 0; k4 < 16; k4++) {
            float4 h4 = *(const float4*)(hrow + k4 * 4);
            acc = fmaf(h4.x, wcol[(k4 * 4 + 0) * ld], acc);
            acc = fmaf(h4.y, wcol[(k4 * 4 + 1) * ld], acc);
            acc = fmaf(h4.z, wcol[(k4 * 4 + 2) * ld], acc);
            acc = fmaf(h4.w, wcol[(k4 * 4 + 3) * ld], acc);
        }
        hpart[tid] = acc;
    }

    // phase 1b: fill pair volume (all threads)
    {
        const float* src = fm + (size_t)b * VOL + ty * WW + tx;
        __half2* dst = pairs + (ty + 1) * PROW + (tx + 1);
        #pragma unroll
        for (int z = 0; z < FF; z++) {
            float val   = src[z * HW];
            float right = (tx < WW - 1) ? src[z * HW + 1] : 0.f;
            dst[z * PLAY] = __floats2half2_rn(val, right);
            if (tx == 0)
                pairs[z * PLAY + (ty + 1) * PROW] = __floats2half2_rn(0.f, val);
        }
    }
    __syncthreads();

    // phase 2: reduce partials + activations + coefficients (threads 0..19)
    if (tid < FF) {
        const int f = tid;
        float4 p0 = *(const float4*)(hpart + 4 * f);
        float4 p1 = *(const float4*)(hpart + 4 * (20 + f));
        float4 p2 = *(const float4*)(hpart + 4 * (40 + 2 * f));
        float4 p3 = *(const float4*)(hpart + 4 * (41 + 2 * f));
        float rs  = bs[f]         + p0.x + p0.y + p0.z + p0.w;
        float rr  = br[f]         + p1.x + p1.y + p1.z + p1.w;
        float rtx = bt[2 * f]     + p2.x + p2.y + p2.z + p2.w;
        float rty = bt[2 * f + 1] + p3.x + p3.y + p3.z + p3.w;

        float sc  = 2.f / (1.f + expf(-rs));
        float ang = tanhf(rr) * PI_F;
        float c   = cosf(ang), s = sinf(ang);
        float txp = tanhf(rtx), typ = tanhf(rty);

        float kk  = sc * ((float)WW / (WW - 1));
        float axx = c * kk,  axy = -s * kk;
        float ayx = s * kk,  ayy =  c * kk;
        float cx = (WW * 0.5f) * (txp - sc * c + sc * s) + (WW - 1) * 0.5f;
        float cy = (HH * 0.5f) * (typ - sc * s - sc * c) + (HH - 1) * 0.5f;

        float iz  = (float)f * ((float)FF / (FF - 1)) - 0.5f;
        float z0f = floorf(iz);
        float wz  = iz - z0f;
        int   z0  = (int)z0f, z1 = z0 + 1;
        float w0  = (z0 >= 0 && z0 < FF) ? (1.f - wz) : 0.f;
        float w1  = (z1 >= 0 && z1 < FF) ? wz         : 0.f;
        int   zb0 = min(max(z0, 0), FF - 1) * PLAY;
        int   zb1 = min(max(z1, 0), FF - 1) * PLAY;

        cfA[f] = make_float4(axx, axy, cx, w0);
        cfB[f] = make_float4(ayx, ayy, cy, w1);
        zb[f]  = make_int2(zb0, zb1);
    }
    __syncthreads();

    // phase 3: sample (R11-proven body)
    const float fx = (float)tx, fy = (float)ty;
    float* outb = out + (size_t)b * VOL + tid;

    #pragma unroll 4
    for (int f = 0; f < FF; f++) {
        float4 A  = cfA[f];
        float4 Bv = cfB[f];
        int2   zo = zb[f];

        float ix = fmaf(A.x,  fx, fmaf(A.y,  fy, A.z));
        float iy = fmaf(Bv.x, fx, fmaf(Bv.y, fy, Bv.z));
        ix = fminf(fmaxf(ix, -1.f), (float)WW);
        iy = fminf(fmaxf(iy, -1.f), (float)HH);

        int   x0 = __float2int_rd(ix);
        int   y0 = __float2int_rd(iy);
        float wx = ix - (float)x0;
        float wy = iy - (float)y0;

        int bo = y0 * PROW + x0 + (PROW + 1);

        float2 f00 = __half22float2(pairs[zo.x + bo]);
        float2 f01 = __half22float2(pairs[zo.x + bo + PROW]);
        float2 f10 = __half22float2(pairs[zo.y + bo]);
        float2 f11 = __half22float2(pairs[zo.y + bo + PROW]);

        float h00 = fmaf(wx, f00.y - f00.x, f00.x);
        float h01 = fmaf(wx, f01.y - f01.x, f01.x);
        float h10 = fmaf(wx, f10.y - f10.x, f10.x);
        float h11 = fmaf(wx, f11.y - f11.x, f11.x);

        float s0 = fmaf(wy, h01 - h00, h00);
        float s1 = fmaf(wy, h11 - h10, h10);

        outb[f * HW] = fmaf(A.w, s0, Bv.w * s1);
    }
}

// ---------------------------------------------------------------------------
// Launch
// ---------------------------------------------------------------------------
extern "C" void kernel_launch(void* const* d_in, const int* in_sizes, int n_in,
                              void* d_out, int out_size)
{
    const float* feature_map = (const float*)d_in[0];
    const float* para_code   = (const float*)d_in[1];
    const float* W1          = (const float*)d_in[2];
    const float* b1          = (const float*)d_in[3];
    const float* Ws          = (const float*)d_in[4];
    const float* bs          = (const float*)d_in[5];
    const float* Wr          = (const float*)d_in[6];
    const float* br          = (const float*)d_in[7];
    const float* Wt          = (const float*)d_in[8];
    const float* bt          = (const float*)d_in[9];
    float*       out         = (float*)d_out;

    int B = in_sizes[1] / PP;
    if (B > MAXB) B = MAXB;

    dim3 g1((B + K1_BM - 1) / K1_BM, PP / K1_BN);
    adaat_hidden_kernel<<<g1, 256>>>(para_code, B, W1, b1);
    adaat_sample_kernel<<<B, dim3(WW, HH)>>>(feature_map, out, bs, br, bt,
                                             Ws, Wr, Wt);
}

// round 16
// speedup vs baseline: 1.3070x; 1.3070x over previous
#include <cuda_runtime.h>
#include <cuda_bf16.h>
#include <cuda_fp16.h>
#include <math.h>

// Problem constants
#define PP   256
#define FF   20
#define HH   18
#define WW   18
#define HW   (HH*WW)      // 324
#define VOL  (FF*HH*WW)   // 6480
#define MAXB 4096
#define PI_F 3.14159f

// Sampler pair volume: per layer 21 rows x 21 half2, 20 layers
#define PROW 21
#define PLAY (PROW*PROW)  // 441
#define PVOL (FF*PLAY)    // 8820 half2 = 35280 B

// Device scratch
#define NG 8
__device__ float g_h[MAXB * PP];            // hidden activations
__device__ float g_part[NG][MAXB * 80];     // head partials per k-slice

// ---------------------------------------------------------------------------
// f32x2 helpers (FFMA2 via PTX)
// ---------------------------------------------------------------------------
typedef unsigned long long u64;

__device__ __forceinline__ u64 pack2(float lo, float hi) {
    u64 d;
    asm("mov.b64 %0, {%1, %2};" : "=l"(d)
        : "r"(__float_as_uint(lo)), "r"(__float_as_uint(hi)));
    return d;
}
__device__ __forceinline__ u64 pack2dup(float v) {
    u64 d;
    asm("mov.b64 %0, {%1, %1};" : "=l"(d) : "r"(__float_as_uint(v)));
    return d;
}
__device__ __forceinline__ u64 fma2(u64 a, u64 b, u64 c) {
    u64 d;
    asm("fma.rn.f32x2 %0, %1, %2, %3;" : "=l"(d) : "l"(a), "l"(b), "l"(c));
    return d;
}
__device__ __forceinline__ float2 unpack2(u64 v) {
    unsigned lo, hi;
    asm("mov.b64 {%0, %1}, %2;" : "=r"(lo), "=r"(hi) : "l"(v));
    float2 f; f.x = __uint_as_float(lo); f.y = __uint_as_float(hi);
    return f;
}

// ---------------------------------------------------------------------------
// Kernel 1: h = relu(pc @ W1 + b1). BM=32, BN=32, BK=32, 128 threads,
// thread tile 4 rows x 2 cols (1 u64 col-pair). grid = (B/32, 8) = 1024
// blocks -> ~6.9 blocks/SM, 27.7 warps/SM (2x R13 occupancy).
// ---------------------------------------------------------------------------
#define K1_BM 32
#define K1_BN 32
#define K1_BK 32
#define K1_S  36

__global__ __launch_bounds__(128) void adaat_hidden_kernel(
    const float* __restrict__ pc, int B,
    const float* __restrict__ W1, const float* __restrict__ b1)
{
    __shared__ float As[K1_BK * K1_S];   // [kk][row]
    __shared__ float Bs[K1_BK * K1_S];   // [kk][col]

    const int b0  = blockIdx.x * K1_BM;
    const int n0  = blockIdx.y * K1_BN;
    const int tid = threadIdx.x;
    const int tc  = tid & 15;      // col pair: cols tc*2, tc*2+1
    const int tr  = tid >> 4;      // row group: rows tr*4 .. +3

    u64 acc[4];
    {
        float2 bj = *(const float2*)(b1 + n0 + tc * 2);
        u64 lo = pack2(bj.x, bj.y);
        #pragma unroll
        for (int i = 0; i < 4; i++) acc[i] = lo;
    }

    for (int kt = 0; kt < PP; kt += K1_BK) {
        // A tile: pc[b0+row][kt+kk] -> As[kk][row]  (1024 elems, 8/thread)
        #pragma unroll
        for (int p = 0; p < 8; p++) {
            int idx = p * 128 + tid;
            int row = idx >> 5, kk = idx & 31;
            float v = (b0 + row < B) ? pc[(size_t)(b0 + row) * PP + kt + kk] : 0.f;
            As[kk * K1_S + row] = v;
        }
        // B tile: W1[kt+kk][n0+col] -> Bs[kk][col]
        #pragma unroll
        for (int p = 0; p < 8; p++) {
            int idx = p * 128 + tid;
            int kk = idx >> 5, col = idx & 31;
            Bs[kk * K1_S + col] = W1[(size_t)(kt + kk) * PP + n0 + col];
        }
        __syncthreads();

        #pragma unroll
        for (int kk = 0; kk < K1_BK; kk++) {
            float4 a = *(const float4*)(As + kk * K1_S + tr * 4);
            float2 w = *(const float2*)(Bs + kk * K1_S + tc * 2);
            u64 wp = pack2(w.x, w.y);
            acc[0] = fma2(pack2dup(a.x), wp, acc[0]);
            acc[1] = fma2(pack2dup(a.y), wp, acc[1]);
            acc[2] = fma2(pack2dup(a.z), wp, acc[2]);
            acc[3] = fma2(pack2dup(a.w), wp, acc[3]);
        }
        __syncthreads();
    }

    #pragma unroll
    for (int i = 0; i < 4; i++) {
        int row = b0 + tr * 4 + i;
        if (row >= B) break;
        float2 v = unpack2(acc[i]);
        float2 o;
        o.x = fmaxf(v.x, 0.f);
        o.y = fmaxf(v.y, 0.f);
        *(float2*)(g_h + (size_t)row * PP + n0 + tc * 2) = o;
    }
}

// ---------------------------------------------------------------------------
// Kernel 2: head partials, k-split NG=8. grid (B/64, 8), 256 threads.
// Block (bx, g): g_part[g][row][80] = h[row][g*32 .. g*32+31] @ Wh-slice.
// ---------------------------------------------------------------------------
#define HS_S 66

__global__ __launch_bounds__(256) void adaat_heads_kernel(
    int B,
    const float* __restrict__ Ws, const float* __restrict__ Wr,
    const float* __restrict__ Wt)
{
    __shared__ float hsl[32 * HS_S];   // [kk][row], 8448 B
    __shared__ float Wh[32 * 80];      // 10240 B

    const int b0  = blockIdx.x * 64;
    const int g   = blockIdx.y;
    const int tid = threadIdx.x;

    // stage h slice: g_h[(b0+row)*PP + g*32 + kk] -> hsl[kk][row]
    #pragma unroll
    for (int p = 0; p < 8; p++) {
        int idx = p * 256 + tid;
        int row = idx >> 5, kk = idx & 31;
        float v = (b0 + row < B) ? g_h[(size_t)(b0 + row) * PP + g * 32 + kk] : 0.f;
        hsl[kk * HS_S + row] = v;
    }
    // stage head-weight slice: Wh[kk][c]
    #pragma unroll
    for (int p = 0; p < 10; p++) {
        int i  = p * 256 + tid;
        int kk = i / 80;
        int c  = i - kk * 80;
        int gk = g * 32 + kk;
        float v;
        if (c < 20)      v = Ws[(size_t)gk * 20 + c];
        else if (c < 40) v = Wr[(size_t)gk * 20 + (c - 20)];
        else             v = Wt[(size_t)gk * 40 + (c - 40)];
        Wh[kk * 80 + c] = v;
    }
    __syncthreads();

    const int row = tid >> 2;     // 0..63
    const int q   = tid & 3;      // col quarter
    float accp[20];
    #pragma unroll
    for (int j = 0; j < 20; j++) accp[j] = 0.f;

    #pragma unroll 2
    for (int kk = 0; kk < 32; kk++) {
        float hv = hsl[kk * HS_S + row];
        const float* wrow = Wh + kk * 80 + q * 20;
        #pragma unroll
        for (int gg = 0; gg < 5; gg++) {
            float4 w = *(const float4*)(wrow + gg * 4);
            accp[gg*4+0] = fmaf(hv, w.x, accp[gg*4+0]);
            accp[gg*4+1] = fmaf(hv, w.y, accp[gg*4+1]);
            accp[gg*4+2] = fmaf(hv, w.z, accp[gg*4+2]);
            accp[gg*4+3] = fmaf(hv, w.w, accp[gg*4+3]);
        }
    }

    if (b0 + row < B) {
        float* dst = g_part[g] + (size_t)(b0 + row) * 80 + q * 20;
        #pragma unroll
        for (int gg = 0; gg < 5; gg++)
            *(float4*)(dst + gg * 4) =
                make_float4(accp[gg*4+0], accp[gg*4+1], accp[gg*4+2], accp[gg*4+3]);
    }
}

// ---------------------------------------------------------------------------
// Kernel 3: trilinear sample — R13-proven body; setup sums NG=8 partials.
// ---------------------------------------------------------------------------
__global__ __launch_bounds__(324) void adaat_sample_kernel(
    const float* __restrict__ fm, float* __restrict__ out,
    const float* __restrict__ bs, const float* __restrict__ br,
    const float* __restrict__ bt)
{
    const int b   = blockIdx.x;
    const int tx  = threadIdx.x;      // 0..17
    const int ty  = threadIdx.y;      // 0..17
    const int tid = ty * WW + tx;

    __shared__ __half2 pairs[PVOL];   // 35280 B
    __shared__ float4  cfA[FF];
    __shared__ float4  cfB[FF];
    __shared__ int2    zb[FF];

    {
        float4* p4 = (float4*)pairs;
        for (int i = tid; i < PVOL / 4; i += HW)
            p4[i] = make_float4(0.f, 0.f, 0.f, 0.f);
    }
    __syncthreads();

    {
        const float* src = fm + (size_t)b * VOL + ty * WW + tx;
        __half2* dst = pairs + (ty + 1) * PROW + (tx + 1);
        #pragma unroll
        for (int z = 0; z < FF; z++) {
            float val   = src[z * HW];
            float right = (tx < WW - 1) ? src[z * HW + 1] : 0.f;
            dst[z * PLAY] = __floats2half2_rn(val, right);
            if (tx == 0)
                pairs[z * PLAY + (ty + 1) * PROW] = __floats2half2_rn(0.f, val);
        }
    }

    if (tid < FF) {
        const int f = tid;
        float rs  = bs[f];
        float rr  = br[f];
        float rtx = bt[2 * f];
        float rty = bt[2 * f + 1];
        #pragma unroll
        for (int p = 0; p < NG; p++) {
            const float* pp = g_part[p] + (size_t)b * 80;
            rs  += pp[f];
            rr  += pp[20 + f];
            rtx += pp[40 + 2 * f];
            rty += pp[41 + 2 * f];
        }
        float sc  = 2.f / (1.f + expf(-rs));
        float ang = tanhf(rr) * PI_F;
        float c   = cosf(ang), s = sinf(ang);
        float txp = tanhf(rtx), typ = tanhf(rty);

        float kk  = sc * ((float)WW / (WW - 1));
        float axx = c * kk,  axy = -s * kk;
        float ayx = s * kk,  ayy =  c * kk;
        float cx = (WW * 0.5f) * (txp - sc * c + sc * s) + (WW - 1) * 0.5f;
        float cy = (HH * 0.5f) * (typ - sc * s - sc * c) + (HH - 1) * 0.5f;

        float iz  = (float)f * ((float)FF / (FF - 1)) - 0.5f;
        float z0f = floorf(iz);
        float wz  = iz - z0f;
        int   z0  = (int)z0f, z1 = z0 + 1;
        float w0  = (z0 >= 0 && z0 < FF) ? (1.f - wz) : 0.f;
        float w1  = (z1 >= 0 && z1 < FF) ? wz         : 0.f;
        int   zb0 = min(max(z0, 0), FF - 1) * PLAY;
        int   zb1 = min(max(z1, 0), FF - 1) * PLAY;

        cfA[f] = make_float4(axx, axy, cx, w0);
        cfB[f] = make_float4(ayx, ayy, cy, w1);
        zb[f]  = make_int2(zb0, zb1);
    }
    __syncthreads();

    const float fx = (float)tx, fy = (float)ty;
    float* outb = out + (size_t)b * VOL + tid;

    #pragma unroll 4
    for (int f = 0; f < FF; f++) {
        float4 A  = cfA[f];
        float4 Bv = cfB[f];
        int2   zo = zb[f];

        float ix = fmaf(A.x,  fx, fmaf(A.y,  fy, A.z));
        float iy = fmaf(Bv.x, fx, fmaf(Bv.y, fy, Bv.z));
        ix = fminf(fmaxf(ix, -1.f), (float)WW);
        iy = fminf(fmaxf(iy, -1.f), (float)HH);

        int   x0 = __float2int_rd(ix);
        int   y0 = __float2int_rd(iy);
        float wx = ix - (float)x0;
        float wy = iy - (float)y0;

        int bo = y0 * PROW + x0 + (PROW + 1);

        float2 f00 = __half22float2(pairs[zo.x + bo]);
        float2 f01 = __half22float2(pairs[zo.x + bo + PROW]);
        float2 f10 = __half22float2(pairs[zo.y + bo]);
        float2 f11 = __half22float2(pairs[zo.y + bo + PROW]);

        float h00 = fmaf(wx, f00.y - f00.x, f00.x);
        float h01 = fmaf(wx, f01.y - f01.x, f01.x);
        float h10 = fmaf(wx, f10.y - f10.x, f10.x);
        float h11 = fmaf(wx, f11.y - f11.x, f11.x);

        float s0 = fmaf(wy, h01 - h00, h00);
        float s1 = fmaf(wy, h11 - h10, h10);

        outb[f * HW] = fmaf(A.w, s0, Bv.w * s1);
    }
}

// ---------------------------------------------------------------------------
// Launch
// ---------------------------------------------------------------------------
extern "C" void kernel_launch(void* const* d_in, const int* in_sizes, int n_in,
                              void* d_out, int out_size)
{
    const float* feature_map = (const float*)d_in[0];
    const float* para_code   = (const float*)d_in[1];
    const float* W1          = (const float*)d_in[2];
    const float* b1          = (const float*)d_in[3];
    const float* Ws          = (const float*)d_in[4];
    const float* bs          = (const float*)d_in[5];
    const float* Wr          = (const float*)d_in[6];
    const float* br          = (const float*)d_in[7];
    const float* Wt          = (const float*)d_in[8];
    const float* bt          = (const float*)d_in[9];
    float*       out         = (float*)d_out;

    int B = in_sizes[1] / PP;
    if (B > MAXB) B = MAXB;

    dim3 g1((B + K1_BM - 1) / K1_BM, PP / K1_BN);
    adaat_hidden_kernel<<<g1, 128>>>(para_code, B, W1, b1);
    dim3 g2((B + 63) / 64, NG);
    adaat_heads_kernel<<<g2, 256>>>(B, Ws, Wr, Wt);
    adaat_sample_kernel<<<B, dim3(WW, HH)>>>(feature_map, out, bs, br, bt);
}

// round 17
// speedup vs baseline: 1.3677x; 1.0465x over previous
#include <cuda_runtime.h>
#include <cuda_bf16.h>
#include <cuda_fp16.h>
#include <math.h>

// Problem constants
#define PP   256
#define FF   20
#define HH   18
#define WW   18
#define HW   (HH*WW)      // 324
#define VOL  (FF*HH*WW)   // 6480
#define MAXB 4096
#define PI_F 3.14159f

// Sampler pair volume: per layer 21 rows x 21 half2, 20 layers
#define PROW 21
#define PLAY (PROW*PROW)  // 441
#define PVOL (FF*PLAY)    // 8820 half2 = 35280 B

// Device scratch
#define NG 4
__device__ float g_h[MAXB * PP];            // hidden activations
__device__ float g_part[NG][MAXB * 80];     // head partials per k-slice

// ---------------------------------------------------------------------------
// f32x2 helpers (FFMA2 via PTX)
// ---------------------------------------------------------------------------
typedef unsigned long long u64;

__device__ __forceinline__ u64 pack2(float lo, float hi) {
    u64 d;
    asm("mov.b64 %0, {%1, %2};" : "=l"(d)
        : "r"(__float_as_uint(lo)), "r"(__float_as_uint(hi)));
    return d;
}
__device__ __forceinline__ u64 pack2dup(float v) {
    u64 d;
    asm("mov.b64 %0, {%1, %1};" : "=l"(d) : "r"(__float_as_uint(v)));
    return d;
}
__device__ __forceinline__ u64 fma2(u64 a, u64 b, u64 c) {
    u64 d;
    asm("fma.rn.f32x2 %0, %1, %2, %3;" : "=l"(d) : "l"(a), "l"(b), "l"(c));
    return d;
}
__device__ __forceinline__ float2 unpack2(u64 v) {
    unsigned lo, hi;
    asm("mov.b64 {%0, %1}, %2;" : "=r"(lo), "=r"(hi) : "l"(v));
    float2 f; f.x = __uint_as_float(lo); f.y = __uint_as_float(hi);
    return f;
}

// ---------------------------------------------------------------------------
// Kernel 1: h = relu(pc @ W1 + b1), double-buffered tiled SGEMM (R13-proven).
// BM=64, BN=64, BK=32, 256 threads, 4x4 thread tile, grid (B/64, 4).
// ---------------------------------------------------------------------------
#define K1_BM 64
#define K1_BN 64
#define K1_BK 32
#define K1_AS 68
#define NKT   (PP / K1_BK)   // 8

__global__ __launch_bounds__(256) void adaat_hidden_kernel(
    const float* __restrict__ pc, int B,
    const float* __restrict__ W1, const float* __restrict__ b1)
{
    __shared__ float As[2][K1_BK * K1_AS];
    __shared__ float Bs[2][K1_BK * K1_AS];

    const int b0  = blockIdx.x * K1_BM;
    const int n0  = blockIdx.y * K1_BN;
    const int tid = threadIdx.x;
    const int tc  = tid & 15;
    const int tr  = tid >> 4;

    float ra[8], rb[8];

    #pragma unroll
    for (int p = 0; p < 8; p++) {
        int idx = p * 256 + tid;
        int row = idx >> 5, kk = idx & 31;
        ra[p] = (b0 + row < B) ? pc[(size_t)(b0 + row) * PP + kk] : 0.f;
    }
    #pragma unroll
    for (int p = 0; p < 8; p++) {
        int idx = p * 256 + tid;
        int kk = idx >> 6, col = idx & 63;
        rb[p] = W1[(size_t)kk * PP + n0 + col];
    }
    #pragma unroll
    for (int p = 0; p < 8; p++) {
        int idx = p * 256 + tid;
        int row = idx >> 5, kk = idx & 31;
        As[0][kk * K1_AS + row] = ra[p];
    }
    #pragma unroll
    for (int p = 0; p < 8; p++) {
        int idx = p * 256 + tid;
        int kk = idx >> 6, col = idx & 63;
        Bs[0][kk * K1_AS + col] = rb[p];
    }
    __syncthreads();

    u64 acc[4][2];
    {
        float4 bj = *(const float4*)(b1 + n0 + tc * 4);
        u64 lo = pack2(bj.x, bj.y), hi = pack2(bj.z, bj.w);
        #pragma unroll
        for (int i = 0; i < 4; i++) { acc[i][0] = lo; acc[i][1] = hi; }
    }

    for (int it = 0; it < NKT; it++) {
        const int cur = it & 1;
        const int nxt = cur ^ 1;

        if (it < NKT - 1) {
            int kt = (it + 1) * K1_BK;
            #pragma unroll
            for (int p = 0; p < 8; p++) {
                int idx = p * 256 + tid;
                int row = idx >> 5, kk = idx & 31;
                ra[p] = (b0 + row < B) ? pc[(size_t)(b0 + row) * PP + kt + kk] : 0.f;
            }
            #pragma unroll
            for (int p = 0; p < 8; p++) {
                int idx = p * 256 + tid;
                int kk = idx >> 6, col = idx & 63;
                rb[p] = W1[(size_t)(kt + kk) * PP + n0 + col];
            }
        }

        #pragma unroll
        for (int kk = 0; kk < K1_BK; kk++) {
            float4 a = *(const float4*)(&As[cur][kk * K1_AS + tr * 4]);
            float4 w = *(const float4*)(&Bs[cur][kk * K1_AS + tc * 4]);
            u64 wlo = pack2(w.x, w.y), whi = pack2(w.z, w.w);
            u64 a0 = pack2dup(a.x), a1 = pack2dup(a.y);
            u64 a2 = pack2dup(a.z), a3 = pack2dup(a.w);
            acc[0][0] = fma2(a0, wlo, acc[0][0]); acc[0][1] = fma2(a0, whi, acc[0][1]);
            acc[1][0] = fma2(a1, wlo, acc[1][0]); acc[1][1] = fma2(a1, whi, acc[1][1]);
            acc[2][0] = fma2(a2, wlo, acc[2][0]); acc[2][1] = fma2(a2, whi, acc[2][1]);
            acc[3][0] = fma2(a3, wlo, acc[3][0]); acc[3][1] = fma2(a3, whi, acc[3][1]);
        }

        if (it < NKT - 1) {
            #pragma unroll
            for (int p = 0; p < 8; p++) {
                int idx = p * 256 + tid;
                int row = idx >> 5, kk = idx & 31;
                As[nxt][kk * K1_AS + row] = ra[p];
            }
            #pragma unroll
            for (int p = 0; p < 8; p++) {
                int idx = p * 256 + tid;
                int kk = idx >> 6, col = idx & 63;
                Bs[nxt][kk * K1_AS + col] = rb[p];
            }
        }
        __syncthreads();
    }

    #pragma unroll
    for (int i = 0; i < 4; i++) {
        int row = b0 + tr * 4 + i;
        if (row >= B) break;
        float2 v0 = unpack2(acc[i][0]);
        float2 v1 = unpack2(acc[i][1]);
        float4 o;
        o.x = fmaxf(v0.x, 0.f); o.y = fmaxf(v0.y, 0.f);
        o.z = fmaxf(v1.x, 0.f); o.w = fmaxf(v1.y, 0.f);
        *(float4*)(g_h + (size_t)row * PP + n0 + tc * 4) = o;
    }
}

// ---------------------------------------------------------------------------
// Kernel 2: head partials, k-split NG=4. grid (B/64, 4), 128 threads.
// Thread tile: 2 rows x 20 cols (FFMA2 row-pair accumulators) ->
// 88 B LDS per 80 MACs (was 4.2 B/MAC with the 1x4 tile).
// ---------------------------------------------------------------------------
#define HS_S 66

__global__ __launch_bounds__(128) void adaat_heads_kernel(
    int B,
    const float* __restrict__ Ws, const float* __restrict__ Wr,
    const float* __restrict__ Wt)
{
    __shared__ float hsl[64 * HS_S];   // [kk][row], 16896 B
    __shared__ float Wh[64 * 80];      // 20480 B

    const int b0  = blockIdx.x * 64;
    const int g   = blockIdx.y;        // k-slice 0..3
    const int tid = threadIdx.x;       // 0..127

    // stage h slice: g_h[(b0+row)*PP + g*64 + kk] -> hsl[kk][row]
    #pragma unroll
    for (int p = 0; p < 32; p++) {
        int idx = p * 128 + tid;       // 0..4095
        int row = idx >> 6, kk = idx & 63;
        float v = (b0 + row < B) ? g_h[(size_t)(b0 + row) * PP + g * 64 + kk] : 0.f;
        hsl[kk * HS_S + row] = v;
    }
    // stage head-weight slice: Wh[kk][c]
    #pragma unroll
    for (int p = 0; p < 40; p++) {
        int i  = p * 128 + tid;        // 0..5119
        int kk = i / 80;
        int c  = i - kk * 80;
        int gk = g * 64 + kk;
        float v;
        if (c < 20)      v = Ws[(size_t)gk * 20 + c];
        else if (c < 40) v = Wr[(size_t)gk * 20 + (c - 20)];
        else             v = Wt[(size_t)gk * 40 + (c - 40)];
        Wh[kk * 80 + c] = v;
    }
    __syncthreads();

    const int rp = tid >> 2;      // row pair 0..31 -> rows rp*2, rp*2+1
    const int q  = tid & 3;       // col quarter -> cols q*20 .. q*20+19

    u64 acc[20];                  // (row0, row1) pairs for 20 cols
    #pragma unroll
    for (int j = 0; j < 20; j++) acc[j] = 0ull;

    #pragma unroll 2
    for (int kk = 0; kk < 64; kk++) {
        float2 h2 = *(const float2*)(hsl + kk * HS_S + rp * 2);
        u64 hp = pack2(h2.x, h2.y);
        const float* wrow = Wh + kk * 80 + q * 20;
        #pragma unroll
        for (int gg = 0; gg < 5; gg++) {
            float4 w = *(const float4*)(wrow + gg * 4);
            acc[gg*4+0] = fma2(hp, pack2dup(w.x), acc[gg*4+0]);
            acc[gg*4+1] = fma2(hp, pack2dup(w.y), acc[gg*4+1]);
            acc[gg*4+2] = fma2(hp, pack2dup(w.z), acc[gg*4+2]);
            acc[gg*4+3] = fma2(hp, pack2dup(w.w), acc[gg*4+3]);
        }
    }

    // write both rows
    #pragma unroll
    for (int r = 0; r < 2; r++) {
        int row = b0 + rp * 2 + r;
        if (row >= B) continue;
        float* dst = g_part[g] + (size_t)row * 80 + q * 20;
        #pragma unroll
        for (int gg = 0; gg < 5; gg++) {
            float2 v0 = unpack2(acc[gg*4+0]);
            float2 v1 = unpack2(acc[gg*4+1]);
            float2 v2 = unpack2(acc[gg*4+2]);
            float2 v3 = unpack2(acc[gg*4+3]);
            float4 o;
            o.x = r ? v0.y : v0.x;
            o.y = r ? v1.y : v1.x;
            o.z = r ? v2.y : v2.x;
            o.w = r ? v3.y : v3.x;
            *(float4*)(dst + gg * 4) = o;
        }
    }
}

// ---------------------------------------------------------------------------
// Kernel 3: trilinear sample — R13-proven body; setup sums NG=4 partials.
// ---------------------------------------------------------------------------
__global__ __launch_bounds__(324) void adaat_sample_kernel(
    const float* __restrict__ fm, float* __restrict__ out,
    const float* __restrict__ bs, const float* __restrict__ br,
    const float* __restrict__ bt)
{
    const int b   = blockIdx.x;
    const int tx  = threadIdx.x;      // 0..17
    const int ty  = threadIdx.y;      // 0..17
    const int tid = ty * WW + tx;

    __shared__ __half2 pairs[PVOL];   // 35280 B
    __shared__ float4  cfA[FF];
    __shared__ float4  cfB[FF];
    __shared__ int2    zb[FF];

    {
        float4* p4 = (float4*)pairs;
        for (int i = tid; i < PVOL / 4; i += HW)
            p4[i] = make_float4(0.f, 0.f, 0.f, 0.f);
    }
    __syncthreads();

    {
        const float* src = fm + (size_t)b * VOL + ty * WW + tx;
        __half2* dst = pairs + (ty + 1) * PROW + (tx + 1);
        #pragma unroll
        for (int z = 0; z < FF; z++) {
            float val   = src[z * HW];
            float right = (tx < WW - 1) ? src[z * HW + 1] : 0.f;
            dst[z * PLAY] = __floats2half2_rn(val, right);
            if (tx == 0)
                pairs[z * PLAY + (ty + 1) * PROW] = __floats2half2_rn(0.f, val);
        }
    }

    if (tid < FF) {
        const int f = tid;
        float rs  = bs[f];
        float rr  = br[f];
        float rtx = bt[2 * f];
        float rty = bt[2 * f + 1];
        #pragma unroll
        for (int p = 0; p < NG; p++) {
            const float* pp = g_part[p] + (size_t)b * 80;
            rs  += pp[f];
            rr  += pp[20 + f];
            rtx += pp[40 + 2 * f];
            rty += pp[41 + 2 * f];
        }
        float sc  = 2.f / (1.f + expf(-rs));
        float ang = tanhf(rr) * PI_F;
        float c   = cosf(ang), s = sinf(ang);
        float txp = tanhf(rtx), typ = tanhf(rty);

        float kk  = sc * ((float)WW / (WW - 1));
        float axx = c * kk,  axy = -s * kk;
        float ayx = s * kk,  ayy =  c * kk;
        float cx = (WW * 0.5f) * (txp - sc * c + sc * s) + (WW - 1) * 0.5f;
        float cy = (HH * 0.5f) * (typ - sc * s - sc * c) + (HH - 1) * 0.5f;

        float iz  = (float)f * ((float)FF / (FF - 1)) - 0.5f;
        float z0f = floorf(iz);
        float wz  = iz - z0f;
        int   z0  = (int)z0f, z1 = z0 + 1;
        float w0  = (z0 >= 0 && z0 < FF) ? (1.f - wz) : 0.f;
        float w1  = (z1 >= 0 && z1 < FF) ? wz         : 0.f;
        int   zb0 = min(max(z0, 0), FF - 1) * PLAY;
        int   zb1 = min(max(z1, 0), FF - 1) * PLAY;

        cfA[f] = make_float4(axx, axy, cx, w0);
        cfB[f] = make_float4(ayx, ayy, cy, w1);
        zb[f]  = make_int2(zb0, zb1);
    }
    __syncthreads();

    const float fx = (float)tx, fy = (float)ty;
    float* outb = out + (size_t)b * VOL + tid;

    #pragma unroll 4
    for (int f = 0; f < FF; f++) {
        float4 A  = cfA[f];
        float4 Bv = cfB[f];
        int2   zo = zb[f];

        float ix = fmaf(A.x,  fx, fmaf(A.y,  fy, A.z));
        float iy = fmaf(Bv.x, fx, fmaf(Bv.y, fy, Bv.z));
        ix = fminf(fmaxf(ix, -1.f), (float)WW);
        iy = fminf(fmaxf(iy, -1.f), (float)HH);

        int   x0 = __float2int_rd(ix);
        int   y0 = __float2int_rd(iy);
        float wx = ix - (float)x0;
        float wy = iy - (float)y0;

        int bo = y0 * PROW + x0 + (PROW + 1);

        float2 f00 = __half22float2(pairs[zo.x + bo]);
        float2 f01 = __half22float2(pairs[zo.x + bo + PROW]);
        float2 f10 = __half22float2(pairs[zo.y + bo]);
        float2 f11 = __half22float2(pairs[zo.y + bo + PROW]);

        float h00 = fmaf(wx, f00.y - f00.x, f00.x);
        float h01 = fmaf(wx, f01.y - f01.x, f01.x);
        float h10 = fmaf(wx, f10.y - f10.x, f10.x);
        float h11 = fmaf(wx, f11.y - f11.x, f11.x);

        float s0 = fmaf(wy, h01 - h00, h00);
        float s1 = fmaf(wy, h11 - h10, h10);

        outb[f * HW] = fmaf(A.w, s0, Bv.w * s1);
    }
}

// ---------------------------------------------------------------------------
// Launch
// ---------------------------------------------------------------------------
extern "C" void kernel_launch(void* const* d_in, const int* in_sizes, int n_in,
                              void* d_out, int out_size)
{
    const float* feature_map = (const float*)d_in[0];
    const float* para_code   = (const float*)d_in[1];
    const float* W1          = (const float*)d_in[2];
    const float* b1          = (const float*)d_in[3];
    const float* Ws          = (const float*)d_in[4];
    const float* bs          = (const float*)d_in[5];
    const float* Wr          = (const float*)d_in[6];
    const float* br          = (const float*)d_in[7];
    const float* Wt          = (const float*)d_in[8];
    const float* bt          = (const float*)d_in[9];
    float*       out         = (float*)d_out;

    int B = in_sizes[1] / PP;
    if (B > MAXB) B = MAXB;

    dim3 g1((B + K1_BM - 1) / K1_BM, PP / K1_BN);
    adaat_hidden_kernel<<<g1, 256>>>(para_code, B, W1, b1);
    dim3 g2((B + 63) / 64, NG);
    adaat_heads_kernel<<<g2, 128>>>(B, Ws, Wr, Wt);
    adaat_sample_kernel<<<B, dim3(WW, HH)>>>(feature_map, out, bs, br, bt);
}